// round 2
// baseline (speedup 1.0000x reference)
#include <cuda_runtime.h>

// Problem constants (fixed shapes)
#define NN   50000
#define EE   640000
#define DIN  64
#define GB_  128
#define GD_  4
#define LB_  256
#define LD_  2
#define GG   1024

// ---------------- device scratch (allowed: __device__ globals) ----------------
__device__ __align__(16) float d_dinv[NN];
__device__ int   d_srcA[EE];
__device__ int   d_dstA[EE];
__device__ __align__(16) float d_enorm[EE];
__device__ __align__(16) float d_h  [(size_t)NN * GB_];
__device__ __align__(16) float d_hw [(size_t)NN * GB_];
__device__ __align__(16) float d_agg[(size_t)NN * GB_];   // also holds BN pre-activations
__device__ __align__(16) float d_stats[2 * GB_];          // colsum, colsumsq
__device__ __align__(16) float d_scale[GB_];
__device__ __align__(16) float d_shift[GB_];
__device__ __align__(16) float d_hp[GG * GB_];
__device__ __align__(16) float d_l0[GG * LB_];
__device__ __align__(16) float d_l1[GG * LB_];
__device__ __align__(16) float d_lscale[LB_];
__device__ __align__(16) float d_lshift[LB_];
__device__ int d_is64;   // 1 if index inputs are int64, 0 if int32

// ---------------- helpers ----------------
__device__ __forceinline__ void red_add_v4(float* p, float a, float b, float c, float d) {
    asm volatile("red.global.add.v4.f32 [%0], {%1, %2, %3, %4};"
                 :: "l"(p), "f"(a), "f"(b), "f"(c), "f"(d) : "memory");
}

// ---------------- dtype detection ----------------
// For int64 data (values < 2^31), every odd 32-bit word is 0.
// For int32 edge indices uniform in [0, 50000), odd words are almost never 0.
__global__ void k_detect(const int* __restrict__ ei32) {
    if (threadIdx.x == 0) {
        int zeros = 0;
        for (int i = 0; i < 64; i++)
            if (ei32[2 * i + 1] == 0) zeros++;
        d_is64 = (zeros >= 60) ? 1 : 0;
    }
}

// ---------------- preprocessing ----------------
__global__ void k_init_deg() {
    int n = blockIdx.x * blockDim.x + threadIdx.x;
    if (n < NN) d_dinv[n] = 1.0f;   // self-loop
}

__global__ void k_prep_edges(const void* __restrict__ ei) {
    int e = blockIdx.x * blockDim.x + threadIdx.x;
    if (e < EE) {
        int s, d;
        if (d_is64) {
            const long long* p = (const long long*)ei;
            s = (int)p[e];
            d = (int)p[EE + e];
        } else {
            const int* p = (const int*)ei;
            s = p[e];
            d = p[EE + e];
        }
        // defensive clamp (avoids wild traps if detection were ever wrong)
        s = min(max(s, 0), NN - 1);
        d = min(max(d, 0), NN - 1);
        d_srcA[e] = s;
        d_dstA[e] = d;
        atomicAdd(&d_dinv[d], 1.0f);
    }
}

__global__ void k_finish_dinv() {
    int n = blockIdx.x * blockDim.x + threadIdx.x;
    if (n < NN) d_dinv[n] = rsqrtf(d_dinv[n]);
}

__global__ void k_enorm() {
    int e = blockIdx.x * blockDim.x + threadIdx.x;
    if (e < EE) d_enorm[e] = d_dinv[d_srcA[e]] * d_dinv[d_dstA[e]];
}

// ---------------- node GEMM: out[N,128] = h[N,K] @ W[K,128] ----------------
template <int K>
__global__ __launch_bounds__(256) void k_gemm_node(const float* __restrict__ h,
                                                   const float* __restrict__ W,
                                                   float* __restrict__ out) {
    extern __shared__ float sm[];
    float* ws = sm;            // [K,128]
    float* hs = sm + K * 128;  // [64,K]
    int t = threadIdx.x;
    int row0 = blockIdx.x * 64;
    int nrows = NN - row0; if (nrows > 64) nrows = 64;

    for (int i = t; i < (K * 128) / 4; i += 256)
        ((float4*)ws)[i] = ((const float4*)W)[i];
    int hv4 = (nrows * K) / 4;
    const float4* hsrc = (const float4*)(h + (size_t)row0 * K);
    for (int i = t; i < (64 * K) / 4; i += 256)
        if (i < hv4) ((float4*)hs)[i] = hsrc[i];
    __syncthreads();

    int warp = t >> 5, lane = t & 31;
    int wr0 = warp * 8;
    float acc[8][4] = {};
    #pragma unroll 2
    for (int k = 0; k < K; k++) {
        float w0 = ws[k * 128 + lane];
        float w1 = ws[k * 128 + lane + 32];
        float w2 = ws[k * 128 + lane + 64];
        float w3 = ws[k * 128 + lane + 96];
        #pragma unroll
        for (int r = 0; r < 8; r++) {
            float hv = hs[(wr0 + r) * K + k];
            acc[r][0] += hv * w0;
            acc[r][1] += hv * w1;
            acc[r][2] += hv * w2;
            acc[r][3] += hv * w3;
        }
    }
    #pragma unroll
    for (int r = 0; r < 8; r++) {
        int row = row0 + wr0 + r;
        if (row < NN) {
            float* o = out + (size_t)row * 128;
            o[lane]      = acc[r][0];
            o[lane + 32] = acc[r][1];
            o[lane + 64] = acc[r][2];
            o[lane + 96] = acc[r][3];
        }
    }
}

// ---------------- edge scatter: agg[dst] += hw[src] * enorm ----------------
__global__ __launch_bounds__(256) void k_scatter() {
    int e = blockIdx.x * 8 + (threadIdx.x >> 5);
    if (e >= EE) return;
    int lane = threadIdx.x & 31;
    int s = d_srcA[e], d = d_dstA[e];
    float w = d_enorm[e];
    float4 v = __ldg((const float4*)(d_hw + (size_t)s * 128) + lane);
    float* a = d_agg + (size_t)d * 128 + lane * 4;
    red_add_v4(a, v.x * w, v.y * w, v.z * w, v.w * w);
}

// ---------------- combine (layer 0, no BN): h = relu(agg + hw*snorm + b) ----------------
__global__ void k_combine0(const float* __restrict__ bias) {
    size_t idx = (size_t)blockIdx.x * 256 + threadIdx.x;
    if (idx < (size_t)NN * 128) {
        int n = (int)(idx >> 7);
        int c = (int)(idx & 127);
        float sn = d_dinv[n];
        float v = d_agg[idx] + d_hw[idx] * sn * sn + bias[c];
        d_h[idx] = fmaxf(v, 0.0f);
    }
}

// ---------------- combine + BN stats ----------------
__global__ __launch_bounds__(256) void k_combine_bn(const float* __restrict__ bias) {
    int t = threadIdx.x;
    int c = t & 127;                 // each thread owns one column (256 % 128 == 0)
    float b = bias[c];
    float ls = 0.f, lss = 0.f;
    size_t base = (size_t)blockIdx.x * 8192 + t;
    #pragma unroll 4
    for (int i = 0; i < 32; i++) {
        size_t idx = base + (size_t)i * 256;
        if (idx < (size_t)NN * 128) {
            int n = (int)(idx >> 7);
            float sn = d_dinv[n];
            float v = d_agg[idx] + d_hw[idx] * sn * sn + b;
            d_agg[idx] = v;
            ls += v; lss += v * v;
        }
    }
    __shared__ float ss[128], sq[128];
    if (t < 128) { ss[t] = ls; sq[t] = lss; }
    __syncthreads();
    if (t >= 128) { ss[c] += ls; sq[c] += lss; }
    __syncthreads();
    if (t < 128) {
        atomicAdd(&d_stats[c], ss[c]);
        atomicAdd(&d_stats[128 + c], sq[c]);
    }
}

__global__ void k_bn_params(const float* __restrict__ gamma, const float* __restrict__ beta) {
    int c = threadIdx.x;  // 128 threads
    float m = d_stats[c] * (1.0f / NN);
    float v = d_stats[128 + c] * (1.0f / NN) - m * m;
    float sc = gamma[c] * rsqrtf(v + 1e-5f);
    d_scale[c] = sc;
    d_shift[c] = beta[c] - m * sc;
}

__global__ void k_bn_apply() {
    size_t idx = (size_t)blockIdx.x * 256 + threadIdx.x;
    if (idx < (size_t)NN * 128) {
        int c = (int)(idx & 127);
        d_h[idx] = fmaxf(d_agg[idx] * d_scale[c] + d_shift[c], 0.0f);
    }
}

// ---------------- pooling: hp[batch[n]] += h[n] ----------------
__global__ __launch_bounds__(256) void k_pool(const void* __restrict__ batch) {
    int n = blockIdx.x * 8 + (threadIdx.x >> 5);
    if (n >= NN) return;
    int lane = threadIdx.x & 31;
    int g;
    if (d_is64) g = (int)((const long long*)batch)[n];
    else        g = ((const int*)batch)[n];
    g = min(max(g, 0), GG - 1);
    float4 v = *((const float4*)(d_h + (size_t)n * 128) + lane);
    red_add_v4(d_hp + (size_t)g * 128 + lane * 4, v.x, v.y, v.z, v.w);
}

// ---------------- head layer 0: l0 = relu(hp @ Wl0 + bl0)  [1024,128]@[128,256] ----------------
__global__ __launch_bounds__(256) void k_head0(const float* __restrict__ W, const float* __restrict__ b) {
    __shared__ float in_s[8 * 128];
    int t = threadIdx.x;
    int g0 = blockIdx.x * 8;
    for (int i = t; i < (8 * 128) / 4; i += 256)
        ((float4*)in_s)[i] = ((const float4*)(d_hp + (size_t)g0 * 128))[i];
    __syncthreads();
    float acc[8] = {};
    for (int k = 0; k < 128; k++) {
        float w = W[k * 256 + t];
        #pragma unroll
        for (int r = 0; r < 8; r++) acc[r] += in_s[r * 128 + k] * w;
    }
    float bb = b[t];
    #pragma unroll
    for (int r = 0; r < 8; r++)
        d_l0[(size_t)(g0 + r) * 256 + t] = fmaxf(acc[r] + bb, 0.0f);
}

// ---------------- head GEMM: l1 = l0 @ W + b  [1024,256]@[256,256] ----------------
__global__ __launch_bounds__(256) void k_headgemm(const float* __restrict__ W, const float* __restrict__ b) {
    __shared__ float in_s[8 * 256];
    int t = threadIdx.x;
    int g0 = blockIdx.x * 8;
    for (int i = t; i < (8 * 256) / 4; i += 256)
        ((float4*)in_s)[i] = ((const float4*)(d_l0 + (size_t)g0 * 256))[i];
    __syncthreads();
    float acc[8] = {};
    for (int k = 0; k < 256; k++) {
        float w = W[k * 256 + t];
        #pragma unroll
        for (int r = 0; r < 8; r++) acc[r] += in_s[r * 256 + k] * w;
    }
    float bb = b[t];
    #pragma unroll
    for (int r = 0; r < 8; r++)
        d_l1[(size_t)(g0 + r) * 256 + t] = acc[r] + bb;
}

// ---------------- head BN: one block per column ----------------
__global__ __launch_bounds__(256) void k_lbn_stats(const float* __restrict__ gamma, const float* __restrict__ beta) {
    int c = blockIdx.x;
    int t = threadIdx.x;
    float ls = 0.f, lss = 0.f;
    for (int r = t; r < GG; r += 256) {
        float v = d_l1[(size_t)r * 256 + c];
        ls += v; lss += v * v;
    }
    __shared__ float ss[256], sq[256];
    ss[t] = ls; sq[t] = lss;
    __syncthreads();
    for (int o = 128; o > 0; o >>= 1) {
        if (t < o) { ss[t] += ss[t + o]; sq[t] += sq[t + o]; }
        __syncthreads();
    }
    if (t == 0) {
        float m = ss[0] * (1.0f / GG);
        float v = sq[0] * (1.0f / GG) - m * m;
        float sc = gamma[c] * rsqrtf(v + 1e-5f);
        d_lscale[c] = sc;
        d_lshift[c] = beta[c] - m * sc;
    }
}

__global__ void k_lbn_apply() {
    size_t idx = (size_t)blockIdx.x * 256 + threadIdx.x;
    if (idx < (size_t)GG * 256) {
        int c = (int)(idx & 255);
        d_l0[idx] = fmaxf(d_l1[idx] * d_lscale[c] + d_lshift[c], 0.0f);
    }
}

// ---------------- final: out = l0 @ Wout + bout  [1024,256]@[256,2] ----------------
__global__ __launch_bounds__(64) void k_final(const float* __restrict__ Wout,
                                              const float* __restrict__ bout,
                                              float* __restrict__ out) {
    int r = blockIdx.x;
    int warp = threadIdx.x >> 5;   // output column (0 or 1)
    int lane = threadIdx.x & 31;
    float s = 0.f;
    for (int k = lane; k < 256; k += 32)
        s += d_l0[(size_t)r * 256 + k] * Wout[k * 2 + warp];
    #pragma unroll
    for (int o = 16; o > 0; o >>= 1) s += __shfl_down_sync(0xffffffffu, s, o);
    if (lane == 0) out[r * 2 + warp] = s + bout[warp];
}

// ---------------- launch ----------------
extern "C" void kernel_launch(void* const* d_in, const int* in_sizes, int n_in,
                              void* d_out, int out_size) {
    const float* x     = (const float*)d_in[0];
    const void*  ei    = d_in[1];
    const void*  batch = d_in[2];
    int base = (n_in >= 18) ? 4 : 3;  // skip num_graphs if present
    const float* W0      = (const float*)d_in[base + 0];
    const float* b0      = (const float*)d_in[base + 1];
    const float* Wg      = (const float*)d_in[base + 2];
    const float* bg      = (const float*)d_in[base + 3];
    const float* gamma_g = (const float*)d_in[base + 4];
    const float* beta_g  = (const float*)d_in[base + 5];
    const float* Wl0     = (const float*)d_in[base + 6];
    const float* bl0     = (const float*)d_in[base + 7];
    const float* Wl      = (const float*)d_in[base + 8];
    const float* bl      = (const float*)d_in[base + 9];
    const float* gamma_l = (const float*)d_in[base + 10];
    const float* beta_l  = (const float*)d_in[base + 11];
    const float* Wout    = (const float*)d_in[base + 12];
    const float* bout    = (const float*)d_in[base + 13];

    void *p_agg, *p_stats, *p_hp, *p_h, *p_hw;
    cudaGetSymbolAddress(&p_agg, d_agg);
    cudaGetSymbolAddress(&p_stats, d_stats);
    cudaGetSymbolAddress(&p_hp, d_hp);
    cudaGetSymbolAddress(&p_h, d_h);
    cudaGetSymbolAddress(&p_hw, d_hw);

    const int SMEM64  = (64 * 128 + 64 * 64) * 4;    // 48 KB
    const int SMEM128 = (128 * 128 + 64 * 128) * 4;  // 96 KB
    cudaFuncSetAttribute(k_gemm_node<64>,  cudaFuncAttributeMaxDynamicSharedMemorySize, SMEM64);
    cudaFuncSetAttribute(k_gemm_node<128>, cudaFuncAttributeMaxDynamicSharedMemorySize, SMEM128);

    // preprocessing: index-dtype detection, degree, dinv, edge norms
    k_detect<<<1, 32>>>((const int*)ei);
    k_init_deg<<<196, 256>>>();
    k_prep_edges<<<2500, 256>>>(ei);
    k_finish_dinv<<<196, 256>>>();
    k_enorm<<<2500, 256>>>();

    // layer 0 (no BN)
    k_gemm_node<64><<<782, 256, SMEM64>>>(x, W0, (float*)p_hw);
    cudaMemsetAsync(p_agg, 0, (size_t)NN * 128 * sizeof(float));
    k_scatter<<<80000, 256>>>();
    k_combine0<<<25000, 256>>>(b0);

    // layers 1..4 (GCN + BN + relu)
    for (int i = 0; i < GD_; i++) {
        k_gemm_node<128><<<782, 256, SMEM128>>>((const float*)p_h, Wg + (size_t)i * 128 * 128, (float*)p_hw);
        cudaMemsetAsync(p_agg, 0, (size_t)NN * 128 * sizeof(float));
        k_scatter<<<80000, 256>>>();
        cudaMemsetAsync(p_stats, 0, 2 * 128 * sizeof(float));
        k_combine_bn<<<782, 256>>>(bg + (size_t)i * 128);
        k_bn_params<<<1, 128>>>(gamma_g + (size_t)i * 128, beta_g + (size_t)i * 128);
        k_bn_apply<<<25000, 256>>>();
    }

    // pooling
    cudaMemsetAsync(p_hp, 0, (size_t)GG * 128 * sizeof(float));
    k_pool<<<6250, 256>>>(batch);

    // head
    k_head0<<<128, 256>>>(Wl0, bl0);
    for (int i = 0; i < LD_; i++) {
        k_headgemm<<<128, 256>>>(Wl + (size_t)i * 256 * 256, bl + (size_t)i * 256);
        k_lbn_stats<<<256, 256>>>(gamma_l + (size_t)i * 256, beta_l + (size_t)i * 256);
        k_lbn_apply<<<1024, 256>>>();
    }
    k_final<<<1024, 64>>>(Wout, bout, (float*)d_out);
}

// round 6
// speedup vs baseline: 1.4878x; 1.4878x over previous
#include <cuda_runtime.h>

// Problem constants (fixed shapes)
#define NN   50000
#define EE   640000
#define DIN  64
#define GB_  128
#define GD_  4
#define LB_  256
#define LD_  2
#define GG   1024

// ---------------- device scratch ----------------
__device__ __align__(16) float d_dinv[NN];
__device__ int   d_ideg[NN];
__device__ int   d_off[NN + 1];
__device__ int   d_cursor[NN];
__device__ int   d_srcA[EE];
__device__ int   d_dstA[EE];
__device__ __align__(16) int2  d_csr[EE];      // {src, float_bits(enorm)}
__device__ __align__(16) float d_hw [(size_t)NN * GB_];
__device__ __align__(16) float d_agg[(size_t)NN * GB_];   // holds h (layer0) or BN pre-activations
__device__ __align__(16) float d_stats[2 * GB_];
__device__ __align__(16) float d_scale[GB_];
__device__ __align__(16) float d_shift[GB_];
__device__ __align__(16) float d_hp[GG * GB_];
__device__ __align__(16) float d_l0[GG * LB_];
__device__ __align__(16) float d_l1[GG * LB_];
__device__ __align__(16) float d_lscale[LB_];
__device__ __align__(16) float d_lshift[LB_];
__device__ int d_is64;

// ---------------- helpers ----------------
__device__ __forceinline__ void red_add_v4(float* p, float a, float b, float c, float d) {
    asm volatile("red.global.add.v4.f32 [%0], {%1, %2, %3, %4};"
                 :: "l"(p), "f"(a), "f"(b), "f"(c), "f"(d) : "memory");
}
__device__ __forceinline__ unsigned long long pack2(float x) {
    unsigned long long r;
    asm("mov.b64 %0, {%1, %1};" : "=l"(r) : "f"(x));
    return r;
}
__device__ __forceinline__ unsigned long long ffma2(unsigned long long a, unsigned long long b,
                                                    unsigned long long c) {
    unsigned long long r;
    asm("fma.rn.f32x2 %0, %1, %2, %3;" : "=l"(r) : "l"(a), "l"(b), "l"(c));
    return r;
}

// ---------------- dtype detection ----------------
__global__ void k_detect(const int* __restrict__ ei32) {
    if (threadIdx.x == 0) {
        int zeros = 0;
        for (int i = 0; i < 64; i++)
            if (ei32[2 * i + 1] == 0) zeros++;
        d_is64 = (zeros >= 60) ? 1 : 0;
    }
}

// ---------------- preprocessing ----------------
__global__ void k_init() {
    int n = blockIdx.x * blockDim.x + threadIdx.x;
    if (n < NN) d_ideg[n] = 0;
}

__global__ void k_prep_edges(const void* __restrict__ ei) {
    int e = blockIdx.x * blockDim.x + threadIdx.x;
    if (e < EE) {
        int s, d;
        if (d_is64) {
            const long long* p = (const long long*)ei;
            s = (int)p[e];
            d = (int)p[EE + e];
        } else {
            const int* p = (const int*)ei;
            s = p[e];
            d = p[EE + e];
        }
        s = min(max(s, 0), NN - 1);
        d = min(max(d, 0), NN - 1);
        d_srcA[e] = s;
        d_dstA[e] = d;
        atomicAdd(&d_ideg[d], 1);
    }
}

__global__ void k_finish_dinv() {
    int n = blockIdx.x * blockDim.x + threadIdx.x;
    if (n < NN) d_dinv[n] = rsqrtf((float)(1 + d_ideg[n]));
}

// single-block exclusive scan of d_ideg -> d_off
__global__ __launch_bounds__(1024) void k_scan() {
    __shared__ int wsum[32];
    __shared__ int s_carry;
    int t = threadIdx.x, lane = t & 31, wid = t >> 5;
    if (t == 0) s_carry = 0;
    __syncthreads();
    for (int base = 0; base < NN; base += 1024) {
        int v = (base + t < NN) ? d_ideg[base + t] : 0;
        int x = v;
        #pragma unroll
        for (int o = 1; o < 32; o <<= 1) {
            int y = __shfl_up_sync(0xffffffffu, x, o);
            if (lane >= o) x += y;
        }
        if (lane == 31) wsum[wid] = x;
        __syncthreads();
        if (wid == 0) {
            int y = wsum[lane];
            #pragma unroll
            for (int o = 1; o < 32; o <<= 1) {
                int z = __shfl_up_sync(0xffffffffu, y, o);
                if (lane >= o) y += z;
            }
            wsum[lane] = y;
        }
        __syncthreads();
        int excl = s_carry + (wid > 0 ? wsum[wid - 1] : 0) + x - v;
        if (base + t < NN) d_off[base + t] = excl;
        __syncthreads();
        if (t == 0) s_carry += wsum[31];
        __syncthreads();
    }
    if (t == 0) d_off[NN] = s_carry;
}

__global__ void k_cursor() {
    int n = blockIdx.x * blockDim.x + threadIdx.x;
    if (n < NN) d_cursor[n] = d_off[n];
}

__global__ void k_csr_fill() {
    int e = blockIdx.x * blockDim.x + threadIdx.x;
    if (e < EE) {
        int s = d_srcA[e], d = d_dstA[e];
        int pos = atomicAdd(&d_cursor[d], 1);
        float w = d_dinv[s] * d_dinv[d];
        d_csr[pos] = make_int2(s, __float_as_int(w));
    }
}

// ---------------- node GEMM: out[N,128] = f(in)[N,K] @ W[K,128] ----------------
// BN=true: input is pre-activation; apply scale/shift + relu while loading.
template <int K, bool BN>
__global__ __launch_bounds__(256) void k_gemm_node(const float* __restrict__ h,
                                                   const float* __restrict__ W,
                                                   float* __restrict__ out) {
    extern __shared__ float sm[];
    float* ws = sm;            // [K][128]
    float* hs = sm + K * 128;  // [64][K]
    int t = threadIdx.x;
    int row0 = blockIdx.x * 64;
    int nrows = NN - row0; if (nrows > 64) nrows = 64;

    for (int i = t; i < (K * 128) / 4; i += 256)
        ((float4*)ws)[i] = ((const float4*)W)[i];

    // h tile load (optional fused BN+relu). col = (t*4) % K is loop-invariant.
    float4 sc4, sh4;
    if (BN) {
        int col = (t * 4) & (K - 1);
        sc4 = *(const float4*)&d_scale[col];
        sh4 = *(const float4*)&d_shift[col];
    }
    int hv4 = (nrows * K) / 4;
    const float4* hsrc = (const float4*)(h + (size_t)row0 * K);
    for (int i = t; i < (64 * K) / 4; i += 256) {
        if (i < hv4) {
            float4 v = hsrc[i];
            if (BN) {
                v.x = fmaxf(v.x * sc4.x + sh4.x, 0.0f);
                v.y = fmaxf(v.y * sc4.y + sh4.y, 0.0f);
                v.z = fmaxf(v.z * sc4.z + sh4.z, 0.0f);
                v.w = fmaxf(v.w * sc4.w + sh4.w, 0.0f);
            }
            ((float4*)hs)[i] = v;
        }
    }
    __syncthreads();

    int warp = t >> 5, lane = t & 31;
    int wr0 = warp * 8;
    // thread owns columns {2l, 2l+1} and {64+2l, 64+2l+1}, 8 rows
    unsigned long long acc[8][2] = {};
    #pragma unroll 2
    for (int k = 0; k < K; k++) {
        unsigned long long wa = *(const unsigned long long*)&ws[k * 128 + 2 * lane];
        unsigned long long wb = *(const unsigned long long*)&ws[k * 128 + 64 + 2 * lane];
        #pragma unroll
        for (int r = 0; r < 8; r++) {
            unsigned long long hv = pack2(hs[(wr0 + r) * K + k]);
            acc[r][0] = ffma2(hv, wa, acc[r][0]);
            acc[r][1] = ffma2(hv, wb, acc[r][1]);
        }
    }
    #pragma unroll
    for (int r = 0; r < 8; r++) {
        int row = row0 + wr0 + r;
        if (row < NN) {
            float* o = out + (size_t)row * 128;
            *(unsigned long long*)(o + 2 * lane)      = acc[r][0];
            *(unsigned long long*)(o + 64 + 2 * lane) = acc[r][1];
        }
    }
}

// ---------------- CSR aggregation: pre[n] = sum_in hw[src]*w + hw[n]*snorm + b ----------------
// MODE 0: write relu(pre) (layer 0).  MODE 1: write pre + accumulate BN stats.
template <int MODE>
__global__ __launch_bounds__(256) void k_agg(const float* __restrict__ bias) {
    __shared__ float ss[128], sq[128];
    int t = threadIdx.x, lane = t & 31, warp = t >> 5;
    if (MODE == 1) {
        if (t < 128) { ss[t] = 0.f; sq[t] = 0.f; }
        __syncthreads();
    }
    float4 bias4 = __ldg((const float4*)bias + lane);
    float4 sum4 = {0, 0, 0, 0}, sq4 = {0, 0, 0, 0};

    int n0 = (blockIdx.x * 8 + warp) * 8;
    for (int j = 0; j < 8; j++) {
        int n = n0 + j;
        if (n >= NN) break;
        float4 acc = bias4;
        int o0 = __ldg(&d_off[n]), o1 = __ldg(&d_off[n + 1]);
        for (int e = o0; e < o1; e++) {
            int2 ed = __ldg(&d_csr[e]);
            float w = __int_as_float(ed.y);
            float4 v = __ldg((const float4*)(d_hw + (size_t)ed.x * 128) + lane);
            acc.x += v.x * w; acc.y += v.y * w; acc.z += v.z * w; acc.w += v.w * w;
        }
        float sn = __ldg(&d_dinv[n]);
        float sn2 = sn * sn;
        float4 vs = *((const float4*)(d_hw + (size_t)n * 128) + lane);
        acc.x += vs.x * sn2; acc.y += vs.y * sn2; acc.z += vs.z * sn2; acc.w += vs.w * sn2;

        float4* dst = (float4*)(d_agg + (size_t)n * 128) + lane;
        if (MODE == 0) {
            acc.x = fmaxf(acc.x, 0.f); acc.y = fmaxf(acc.y, 0.f);
            acc.z = fmaxf(acc.z, 0.f); acc.w = fmaxf(acc.w, 0.f);
            *dst = acc;
        } else {
            *dst = acc;
            sum4.x += acc.x; sum4.y += acc.y; sum4.z += acc.z; sum4.w += acc.w;
            sq4.x += acc.x * acc.x; sq4.y += acc.y * acc.y;
            sq4.z += acc.z * acc.z; sq4.w += acc.w * acc.w;
        }
    }
    if (MODE == 1) {
        int c = lane * 4;
        atomicAdd(&ss[c + 0], sum4.x); atomicAdd(&ss[c + 1], sum4.y);
        atomicAdd(&ss[c + 2], sum4.z); atomicAdd(&ss[c + 3], sum4.w);
        atomicAdd(&sq[c + 0], sq4.x);  atomicAdd(&sq[c + 1], sq4.y);
        atomicAdd(&sq[c + 2], sq4.z);  atomicAdd(&sq[c + 3], sq4.w);
        __syncthreads();
        if (t < 128) {
            atomicAdd(&d_stats[t], ss[t]);
            atomicAdd(&d_stats[128 + t], sq[t]);
        }
    }
}

__global__ void k_bn_params(const float* __restrict__ gamma, const float* __restrict__ beta) {
    int c = threadIdx.x;  // 128 threads
    float m = d_stats[c] * (1.0f / NN);
    float v = d_stats[128 + c] * (1.0f / NN) - m * m;
    float sc = gamma[c] * rsqrtf(v + 1e-5f);
    d_scale[c] = sc;
    d_shift[c] = beta[c] - m * sc;
}

// ---------------- fused BN-apply + pooling (final GCN layer) ----------------
__global__ __launch_bounds__(256) void k_bnpool(const void* __restrict__ batch) {
    int n = blockIdx.x * 8 + (threadIdx.x >> 5);
    if (n >= NN) return;
    int lane = threadIdx.x & 31;
    int g;
    if (d_is64) g = (int)((const long long*)batch)[n];
    else        g = ((const int*)batch)[n];
    g = min(max(g, 0), GG - 1);
    int c = lane * 4;
    float4 sc = *(const float4*)&d_scale[c];
    float4 sh = *(const float4*)&d_shift[c];
    float4 v = *((const float4*)(d_agg + (size_t)n * 128) + lane);
    v.x = fmaxf(v.x * sc.x + sh.x, 0.f);
    v.y = fmaxf(v.y * sc.y + sh.y, 0.f);
    v.z = fmaxf(v.z * sc.z + sh.z, 0.f);
    v.w = fmaxf(v.w * sc.w + sh.w, 0.f);
    red_add_v4(d_hp + (size_t)g * 128 + c, v.x, v.y, v.z, v.w);
}

// ---------------- head layer 0: l0 = relu(hp @ Wl0 + bl0)  [1024,128]@[128,256] ----------------
__global__ __launch_bounds__(256) void k_head0(const float* __restrict__ W, const float* __restrict__ b) {
    __shared__ float in_s[8 * 128];
    int t = threadIdx.x;
    int g0 = blockIdx.x * 8;
    for (int i = t; i < (8 * 128) / 4; i += 256)
        ((float4*)in_s)[i] = ((const float4*)(d_hp + (size_t)g0 * 128))[i];
    __syncthreads();
    float acc[8] = {};
    for (int k = 0; k < 128; k++) {
        float w = W[k * 256 + t];
        #pragma unroll
        for (int r = 0; r < 8; r++) acc[r] += in_s[r * 128 + k] * w;
    }
    float bb = b[t];
    #pragma unroll
    for (int r = 0; r < 8; r++)
        d_l0[(size_t)(g0 + r) * 256 + t] = fmaxf(acc[r] + bb, 0.0f);
}

// ---------------- head GEMM: l1 = l0 @ W + b  [1024,256]@[256,256] ----------------
__global__ __launch_bounds__(256) void k_headgemm(const float* __restrict__ W, const float* __restrict__ b) {
    __shared__ float in_s[8 * 256];
    int t = threadIdx.x;
    int g0 = blockIdx.x * 8;
    for (int i = t; i < (8 * 256) / 4; i += 256)
        ((float4*)in_s)[i] = ((const float4*)(d_l0 + (size_t)g0 * 256))[i];
    __syncthreads();
    float acc[8] = {};
    for (int k = 0; k < 256; k++) {
        float w = W[k * 256 + t];
        #pragma unroll
        for (int r = 0; r < 8; r++) acc[r] += in_s[r * 256 + k] * w;
    }
    float bb = b[t];
    #pragma unroll
    for (int r = 0; r < 8; r++)
        d_l1[(size_t)(g0 + r) * 256 + t] = acc[r] + bb;
}

// ---------------- head BN: one block per column ----------------
__global__ __launch_bounds__(256) void k_lbn_stats(const float* __restrict__ gamma, const float* __restrict__ beta) {
    int c = blockIdx.x;
    int t = threadIdx.x;
    float ls = 0.f, lss = 0.f;
    for (int r = t; r < GG; r += 256) {
        float v = d_l1[(size_t)r * 256 + c];
        ls += v; lss += v * v;
    }
    __shared__ float ss[256], sq[256];
    ss[t] = ls; sq[t] = lss;
    __syncthreads();
    for (int o = 128; o > 0; o >>= 1) {
        if (t < o) { ss[t] += ss[t + o]; sq[t] += sq[t + o]; }
        __syncthreads();
    }
    if (t == 0) {
        float m = ss[0] * (1.0f / GG);
        float v = sq[0] * (1.0f / GG) - m * m;
        float sc = gamma[c] * rsqrtf(v + 1e-5f);
        d_lscale[c] = sc;
        d_lshift[c] = beta[c] - m * sc;
    }
}

__global__ void k_lbn_apply() {
    size_t idx = (size_t)blockIdx.x * 256 + threadIdx.x;
    if (idx < (size_t)GG * 256) {
        int c = (int)(idx & 255);
        d_l0[idx] = fmaxf(d_l1[idx] * d_lscale[c] + d_lshift[c], 0.0f);
    }
}

// ---------------- final: out = l0 @ Wout + bout  [1024,256]@[256,2] ----------------
__global__ __launch_bounds__(64) void k_final(const float* __restrict__ Wout,
                                              const float* __restrict__ bout,
                                              float* __restrict__ out) {
    int r = blockIdx.x;
    int warp = threadIdx.x >> 5;
    int lane = threadIdx.x & 31;
    float s = 0.f;
    for (int k = lane; k < 256; k += 32)
        s += d_l0[(size_t)r * 256 + k] * Wout[k * 2 + warp];
    #pragma unroll
    for (int o = 16; o > 0; o >>= 1) s += __shfl_down_sync(0xffffffffu, s, o);
    if (lane == 0) out[r * 2 + warp] = s + bout[warp];
}

// ---------------- launch ----------------
extern "C" void kernel_launch(void* const* d_in, const int* in_sizes, int n_in,
                              void* d_out, int out_size) {
    const float* x     = (const float*)d_in[0];
    const void*  ei    = d_in[1];
    const void*  batch = d_in[2];
    int base = (n_in >= 18) ? 4 : 3;
    const float* W0      = (const float*)d_in[base + 0];
    const float* b0      = (const float*)d_in[base + 1];
    const float* Wg      = (const float*)d_in[base + 2];
    const float* bg      = (const float*)d_in[base + 3];
    const float* gamma_g = (const float*)d_in[base + 4];
    const float* beta_g  = (const float*)d_in[base + 5];
    const float* Wl0     = (const float*)d_in[base + 6];
    const float* bl0     = (const float*)d_in[base + 7];
    const float* Wl      = (const float*)d_in[base + 8];
    const float* bl      = (const float*)d_in[base + 9];
    const float* gamma_l = (const float*)d_in[base + 10];
    const float* beta_l  = (const float*)d_in[base + 11];
    const float* Wout    = (const float*)d_in[base + 12];
    const float* bout    = (const float*)d_in[base + 13];

    void *p_stats, *p_hp, *p_agg, *p_hw;
    cudaGetSymbolAddress(&p_stats, d_stats);
    cudaGetSymbolAddress(&p_hp, d_hp);
    cudaGetSymbolAddress(&p_agg, d_agg);
    cudaGetSymbolAddress(&p_hw, d_hw);

    const int SMEM64  = (64 * 128 + 64 * 64) * 4;    // 48 KB
    const int SMEM128 = (128 * 128 + 64 * 128) * 4;  // 96 KB
    cudaFuncSetAttribute(k_gemm_node<64, false>,  cudaFuncAttributeMaxDynamicSharedMemorySize, SMEM64);
    cudaFuncSetAttribute(k_gemm_node<128, false>, cudaFuncAttributeMaxDynamicSharedMemorySize, SMEM128);
    cudaFuncSetAttribute(k_gemm_node<128, true>,  cudaFuncAttributeMaxDynamicSharedMemorySize, SMEM128);

    // preprocessing: dtype detect, degrees, dinv, CSR build
    k_detect<<<1, 32>>>((const int*)ei);
    k_init<<<196, 256>>>();
    k_prep_edges<<<2500, 256>>>(ei);
    k_finish_dinv<<<196, 256>>>();
    k_scan<<<1, 1024>>>();
    k_cursor<<<196, 256>>>();
    k_csr_fill<<<2500, 256>>>();

    // layer 0 (no BN): agg writes relu result into d_agg
    k_gemm_node<64, false><<<782, 256, SMEM64>>>(x, W0, (float*)p_hw);
    k_agg<0><<<782, 256>>>(b0);

    // layers 1..4 (GCN + BN + relu, BN applied lazily in next consumer)
    for (int i = 0; i < GD_; i++) {
        if (i == 0)
            k_gemm_node<128, false><<<782, 256, SMEM128>>>((const float*)p_agg, Wg, (float*)p_hw);
        else
            k_gemm_node<128, true><<<782, 256, SMEM128>>>((const float*)p_agg,
                                                          Wg + (size_t)i * 128 * 128, (float*)p_hw);
        cudaMemsetAsync(p_stats, 0, 2 * 128 * sizeof(float));
        k_agg<1><<<782, 256>>>(bg + (size_t)i * 128);
        k_bn_params<<<1, 128>>>(gamma_g + (size_t)i * 128, beta_g + (size_t)i * 128);
    }

    // fused BN-apply + pooling
    cudaMemsetAsync(p_hp, 0, (size_t)GG * 128 * sizeof(float));
    k_bnpool<<<6250, 256>>>(batch);

    // head
    k_head0<<<128, 256>>>(Wl0, bl0);
    for (int i = 0; i < LD_; i++) {
        k_headgemm<<<128, 256>>>(Wl + (size_t)i * 256 * 256, bl + (size_t)i * 256);
        k_lbn_stats<<<256, 256>>>(gamma_l + (size_t)i * 256, beta_l + (size_t)i * 256);
        k_lbn_apply<<<1024, 256>>>();
    }
    k_final<<<1024, 64>>>(Wout, bout, (float*)d_out);
}